// round 8
// baseline (speedup 1.0000x reference)
#include <cuda_runtime.h>
#include <math.h>

#define TWO_PI 6.283185307179586f
#define EPS 1e-6f
#define NEG_HALF_LOG2E (-0.7213475204444817f)

typedef unsigned long long u64;

// ---------------- device scratch ----------------
#define MAXM 120000
#define MAXS 4096
#define MAXROWS 320

__device__ float g_PX[MAXM], g_PY[MAXM];
__device__ float g_EA[MAXM], g_EB[MAXM], g_EC[MAXM], g_W[MAXM];
__device__ float g_C00[MAXM], g_C01[MAXM], g_C11[MAXM];

__device__ float g_SW[MAXS], g_SPX[MAXS], g_SPY[MAXS];
__device__ float g_SC00[MAXS], g_SC01[MAXS], g_SC11[MAXS];

__device__ float g_TOT[MAXROWS], g_SIG[MAXROWS];
__device__ int g_tick = 0;

__device__ __forceinline__ float fast_exp2(float x) {
    float y; asm("ex2.approx.ftz.f32 %0, %1;" : "=f"(y) : "f"(x)); return y;
}
__device__ __forceinline__ float fast_sqrt(float x) {
    float y; asm("sqrt.approx.ftz.f32 %0, %1;" : "=f"(y) : "f"(x)); return y;
}
__device__ __forceinline__ float fast_rcp(float x) {
    float y; asm("rcp.approx.ftz.f32 %0, %1;" : "=f"(y) : "f"(x)); return y;
}

// ---- packed f32x2 helpers ----
__device__ __forceinline__ u64 pk2(float lo, float hi) {
    u64 r; asm("mov.b64 %0, {%1, %2};" : "=l"(r) : "f"(lo), "f"(hi)); return r;
}
__device__ __forceinline__ void upk2(u64 v, float& lo, float& hi) {
    asm("mov.b64 {%0, %1}, %2;" : "=f"(lo), "=f"(hi) : "l"(v));
}
__device__ __forceinline__ u64 add2(u64 a, u64 b) {
    u64 r; asm("add.rn.f32x2 %0, %1, %2;" : "=l"(r) : "l"(a), "l"(b)); return r;
}
__device__ __forceinline__ u64 mul2(u64 a, u64 b) {
    u64 r; asm("mul.rn.f32x2 %0, %1, %2;" : "=l"(r) : "l"(a), "l"(b)); return r;
}
__device__ __forceinline__ u64 fma2(u64 a, u64 b, u64 c) {
    u64 r; asm("fma.rn.f32x2 %0, %1, %2, %3;" : "=l"(r) : "l"(a), "l"(b), "l"(c)); return r;
}

// ---------------- conv with fused batchnorm prologue ----------------
// grid: (ceil(Lo*Li*Nd*Nk/256), B). first=1: input bn (per-gaussian, per-b);
// else: per-li scale from mean-over-batch of g_TOT. Covariances are symmetric
// throughout the net (inputs and kernels are), so only c00/c01/c11 are stored.
__global__ void k_conv(const float* __restrict__ in_x, const float* __restrict__ kern,
                       int Li, int Nd, int Lo, int Nk, int first) {
    __shared__ float s_scl[8];
    __shared__ float s_red[64];
    const int tid = threadIdx.x;
    const int b = blockIdx.y;

    if (first) {
        if (tid < 64) {
            const float* m = in_x + (b * 64 + tid) * 7;
            float det = m[3] * m[6] - m[4] * m[5];
            s_red[tid] = fabsf(m[0] * TWO_PI * fast_sqrt(fmaxf(det, EPS)));
        }
        __syncthreads();
        if (tid < 32) {
            float v = s_red[tid] + s_red[tid + 32];
            for (int o = 16; o > 0; o >>= 1) v += __shfl_xor_sync(0xffffffffu, v, o);
            if (tid == 0) s_scl[0] = 1.0f / (v + EPS);
        }
    } else {
        if (tid < Li * 32) {
            int li = tid >> 5, bb = tid & 31;
            float v = g_TOT[bb * Li + li];
            for (int o = 16; o > 0; o >>= 1) v += __shfl_xor_sync(0xffffffffu, v, o);
            if ((tid & 31) == 0) s_scl[li] = 1.0f / (v * (1.0f / 32.0f) + EPS);
        }
    }
    __syncthreads();

    int perB = Lo * Li * Nd * Nk;
    int i = blockIdx.x * 256 + tid;
    if (i >= perB) return;
    int nk = i % Nk; int t = i / Nk;
    int nd = t % Nd; t /= Nd;
    int li = t % Li; int lo = t / Li;

    int di = (b * Li + li) * Nd + nd;
    float wd, pdx, pdy, d00, d01, d10, d11;
    if (first) {
        const float* m = in_x + di * 7;
        wd = m[0] * s_scl[0]; pdx = m[1]; pdy = m[2];
        d00 = m[3]; d01 = m[4]; d10 = m[5]; d11 = m[6];
    } else {
        wd = g_SW[di] * s_scl[li];
        pdx = g_SPX[di]; pdy = g_SPY[di];
        d00 = g_SC00[di]; d01 = g_SC01[di]; d10 = d01; d11 = g_SC11[di];
    }

    const float* kp = kern + (((lo * Li + li) * Nk) + nk) * 7;
    float wk = kp[0], pkx = kp[1], pky = kp[2];
    float k00 = kp[3], k01 = kp[4], k10 = kp[5], k11 = kp[6];

    float s00 = d00 + k00, s01 = d01 + k01, s10 = d10 + k10, s11 = d11 + k11;
    float dd = d00 * d11 - d01 * d10;
    float dk = k00 * k11 - k01 * k10;
    float ds = s00 * s11 - s01 * s10;
    float inv = fast_rcp(fmaxf(ds, EPS));
    float ws = wd * wk * TWO_PI * fast_sqrt(dd * dk * inv);

    int o = (b * Lo + lo) * (Li * Nd * Nk) + (li * Nd + nd) * Nk + nk;
    g_W[o] = ws;
    g_PX[o] = pdx + pkx; g_PY[o] = pdy + pky;
    g_C00[o] = s00; g_C01[o] = s01; g_C11[o] = s11;
    g_EA[o] = NEG_HALF_LOG2E * s11 * inv;
    g_EB[o] = -NEG_HALF_LOG2E * (s01 + s10) * inv;
    g_EC[o] = NEG_HALF_LOG2E * s00 * inv;
}

// ================= fused eval + topk: one block per row =================
// Each thread evaluates k0=tid and k1=tid+T (2 k's share every tile load).
// w2 -> u64 key in smem (no global w2). Then two-level rank select in the same
// block: level 1 per-warp 64-wide chunk rank, level 2 exact among candidates.
// Layer 3 also runs the ticket-fused finale (batchnorm + integrate + log_softmax).
__global__ void k_evaltopk(int N, int Lo, int nch, int nsel, int do_final, int rows,
                           const float* __restrict__ bias, float* __restrict__ out) {
    extern __shared__ __align__(16) float sh[];
    const int Npad = (N + 1) & ~1;
    const int NC = nch * 64;
    const int half = Npad >> 1;
    float* sAf = sh;            // (px,px,py,py)
    float* sBf = sh + 2 * Npad; // (ea,ea,eb,eb)
    float* sCf = sh + 4 * Npad; // (ec,ec,w,w)
    u64* keys = (u64*)(sh + 6 * Npad);  // NC entries

    __shared__ __align__(16) u64 sCand[136];
    __shared__ int s_cnt;
    __shared__ float s_out[64];
    __shared__ int s_last;
    __shared__ float scl[10];
    __shared__ float logit[320];

    const int tid = threadIdx.x;
    const int T = blockDim.x;
    const int row = blockIdx.x;
    const int lo = row % Lo;
    const int base = row * N;

    if (tid == 0) s_cnt = 0;

    // ---- tile load (pair-interleaved) ----
    for (int n = tid; n < Npad; n += T) {
        int j4 = (n >> 1) * 4 + (n & 1);
        if (n < N) {
            int g = base + n;
            sAf[j4] = g_PX[g]; sAf[j4 + 2] = g_PY[g];
            sBf[j4] = g_EA[g]; sBf[j4 + 2] = g_EB[g];
            sCf[j4] = g_EC[g]; sCf[j4 + 2] = g_W[g];
        } else {
            sAf[j4] = 0.0f; sAf[j4 + 2] = 0.0f;
            sBf[j4] = 0.0f; sBf[j4 + 2] = 0.0f;
            sCf[j4] = 0.0f; sCf[j4 + 2] = 0.0f;
        }
    }
    for (int n = N + tid; n < NC; n += T) keys[n] = 0ull;  // pad keys
    __syncthreads();

    // ---- eval: 2 k's per thread ----
    {
        const int k0 = tid;            // always < N (T < N for all layers)
        const int k1 = tid + T;
        const int k1c = (k1 < N) ? k1 : 0;
        int k04 = (k0 >> 1) * 4 + (k0 & 1);
        int k14 = (k1c >> 1) * 4 + (k1c & 1);
        float kx0 = sAf[k04], ky0 = sAf[k04 + 2], w0 = sCf[k04 + 2];
        float kx1 = sAf[k14], ky1 = sAf[k14 + 2], w1 = sCf[k14 + 2];
        u64 nkx0 = pk2(-kx0, -kx0), nky0 = pk2(-ky0, -ky0);
        u64 nkx1 = pk2(-kx1, -kx1), nky1 = pk2(-ky1, -ky1);
        u64 acc0 = 0ull, acc1 = 0ull;

        const float4* sA = (const float4*)sAf;
        const float4* sB = (const float4*)sBf;
        const float4* sC = (const float4*)sCf;

        #pragma unroll 4
        for (int j = 0; j < half; j++) {
            float4 a = sA[j];
            float4 bq = sB[j];
            float4 c = sC[j];
            u64 px2 = *(const u64*)&a.x;  u64 py2 = *(const u64*)&a.z;
            u64 ea2 = *(const u64*)&bq.x; u64 eb2 = *(const u64*)&bq.z;
            u64 ec2 = *(const u64*)&c.x;  u64 w2p = *(const u64*)&c.z;

            u64 dx0 = add2(px2, nkx0);
            u64 dy0 = add2(py2, nky0);
            u64 u0  = fma2(ea2, dx0, mul2(eb2, dy0));
            u64 md0 = fma2(dx0, u0, mul2(mul2(ec2, dy0), dy0));
            u64 dx1 = add2(px2, nkx1);
            u64 dy1 = add2(py2, nky1);
            u64 u1  = fma2(ea2, dx1, mul2(eb2, dy1));
            u64 md1 = fma2(dx1, u1, mul2(mul2(ec2, dy1), dy1));
            float m0, m1, m2, m3;
            upk2(md0, m0, m1); upk2(md1, m2, m3);
            u64 e0 = pk2(fast_exp2(m0), fast_exp2(m1));
            u64 e1 = pk2(fast_exp2(m2), fast_exp2(m3));
            acc0 = fma2(w2p, e0, acc0);
            acc1 = fma2(w2p, e1, acc1);
        }

        float bs = bias[lo];
        float a0, a1; upk2(acc0, a0, a1);
        float v0 = a0 + a1 + bs;
        float w20 = w0 * (fmaxf(v0, 0.0f) * fast_rcp(fabsf(v0) + EPS));
        keys[k0] = ((u64)__float_as_uint(fabsf(w20)) << 32) | (u64)(unsigned)(~(unsigned)k0);
        if (k1 < N) {
            float b0, b1v; upk2(acc1, b0, b1v);
            float v1 = b0 + b1v + bs;
            float w21 = w1 * (fmaxf(v1, 0.0f) * fast_rcp(fabsf(v1) + EPS));
            keys[k1] = ((u64)__float_as_uint(fabsf(w21)) << 32) | (u64)(unsigned)(~(unsigned)k1);
        }
    }
    __syncthreads();

    // ---- level 1: per-warp chunk rank (warp w handles chunk w) ----
    {
        int w = tid >> 5, lane = tid & 31;
        if (w < nch) {
            int kb = w << 6;
            u64 k0 = keys[kb + lane];
            u64 k1 = keys[kb + lane + 32];
            int r0 = 0, r1 = 0;
            const ulonglong2* Q = (const ulonglong2*)(keys + kb);
            #pragma unroll 8
            for (int j = 0; j < 32; j++) {
                ulonglong2 q = Q[j];
                r0 += (int)(q.x > k0) + (int)(q.y > k0);
                r1 += (int)(q.x > k1) + (int)(q.y > k1);
            }
            if (kb + lane < N && r0 < nsel)      { int s = atomicAdd(&s_cnt, 1); sCand[s] = k0; }
            if (kb + lane + 32 < N && r1 < nsel) { int s = atomicAdd(&s_cnt, 1); sCand[s] = k1; }
        }
    }
    __syncthreads();
    int m = s_cnt;
    if (tid == 0 && (m & 1)) sCand[m] = 0ull;
    __syncthreads();

    // ---- level 2: exact rank among candidates + gather ----
    {
        int mq = (m + 1) >> 1;
        const ulonglong2* Q = (const ulonglong2*)sCand;
        for (int i = tid; i < m; i += T) {
            u64 mykey = sCand[i];
            int rank = 0;
            #pragma unroll 4
            for (int j = 0; j < mq; j++) {
                ulonglong2 q = Q[j];
                rank += (int)(q.x > mykey) + (int)(q.y > mykey);
            }
            if (rank < nsel) {
                int n = (int)(~(unsigned)mykey);
                int n4 = (n >> 1) * 4 + (n & 1);
                unsigned hi = (unsigned)(mykey >> 32);
                unsigned sgn = __float_as_uint(sCf[n4 + 2]) & 0x80000000u;
                float w2 = __uint_as_float(hi | sgn);
                int src = base + n;
                int dst = row * nsel + rank;
                float c00 = g_C00[src], c01 = g_C01[src], c11 = g_C11[src];
                g_SW[dst] = w2;
                g_SPX[dst] = sAf[n4]; g_SPY[dst] = sAf[n4 + 2];
                g_SC00[dst] = c00; g_SC01[dst] = c01; g_SC11[dst] = c11;
                float I = w2 * TWO_PI * fast_sqrt(fmaxf(c00 * c11 - c01 * c01, EPS));
                s_out[rank] = fabsf(I);
                s_out[32 + rank] = I;
            }
        }
    }
    __syncthreads();
    if (tid == 0) {
        float tot = 0.0f, sg = 0.0f;
        for (int t = 0; t < nsel; t++) { tot += s_out[t]; sg += s_out[32 + t]; }
        g_TOT[row] = tot;
        if (do_final) g_SIG[row] = sg;
    }

    if (!do_final) return;

    // ---- fused finale: last block does batchnorm + integrate + log_softmax ----
    if (tid == 0) {
        __threadfence();
        int t = atomicAdd(&g_tick, 1);
        s_last = (t == rows - 1) ? 1 : 0;
        if (s_last) g_tick = 0;
    }
    __syncthreads();
    if (!s_last) return;
    __threadfence();

    if (tid < 10) {
        float t = 0.0f;
        for (int b = 0; b < 32; b++) t += g_TOT[b * 10 + tid];
        scl[tid] = 1.0f / (t / 32.0f + EPS);
    }
    __syncthreads();
    for (int i = tid; i < 320; i += T) logit[i] = g_SIG[i] * scl[i % 10];
    __syncthreads();
    if (tid < 32) {
        int b = tid;
        float mx = -INFINITY;
        for (int l = 0; l < 10; l++) mx = fmaxf(mx, logit[b * 10 + l]);
        float se = 0.0f;
        for (int l = 0; l < 10; l++) se += expf(logit[b * 10 + l] - mx);
        float lse = mx + logf(se);
        for (int l = 0; l < 10; l++) out[b * 10 + l] = logit[b * 10 + l] - lse;
    }
}

static inline int et_smem(int N, int nch) {
    int Npad = (N + 1) & ~1;
    return 24 * Npad + 8 * nch * 64;
}

extern "C" void kernel_launch(void* const* d_in, const int* in_sizes, int n_in,
                              void* d_out, int out_size) {
    const float* in_x = (const float*)d_in[0];
    const float* k1 = (const float*)d_in[1];
    const float* k2 = (const float*)d_in[2];
    const float* k3 = (const float*)d_in[3];
    const float* b1 = (const float*)d_in[4];
    const float* b2 = (const float*)d_in[5];
    const float* b3 = (const float*)d_in[6];
    float* out = (float*)d_out;

    // ===== layer 1: Li=1, Nd=64, Lo=5, Nk=5 -> N=320, rows=160, nsel=25 =====
    {
        int Li = 1, Nd = 64, Lo = 5, Nk = 5;
        int N = 320, rows = 160, perB = Lo * N;
        k_conv<<<dim3((perB + 255) / 256, 32), 256>>>(in_x, k1, Li, Nd, Lo, Nk, 1);
        k_evaltopk<<<rows, 192, et_smem(N, 5)>>>(N, Lo, 5, 25, 0, rows, b1, out);
    }

    // ===== layer 2: Li=5, Nd=25, Lo=6, Nk=5 -> N=625, rows=192, nsel=12 =====
    {
        int Li = 5, Nd = 25, Lo = 6, Nk = 5;
        int N = 625, rows = 192, perB = Lo * Li * Nd * Nk;
        k_conv<<<dim3((perB + 255) / 256, 32), 256>>>(in_x, k2, Li, Nd, Lo, Nk, 0);
        k_evaltopk<<<rows, 512, et_smem(N, 10)>>>(N, Lo, 10, 12, 0, rows, b2, out);
    }

    // ===== layer 3: Li=6, Nd=12, Lo=10, Nk=5 -> N=360, rows=320, nsel=5 =====
    {
        int Li = 6, Nd = 12, Lo = 10, Nk = 5;
        int N = 360, rows = 320, perB = Lo * Li * Nd * Nk;
        k_conv<<<dim3((perB + 255) / 256, 32), 256>>>(in_x, k3, Li, Nd, Lo, Nk, 0);
        k_evaltopk<<<rows, 192, et_smem(N, 6)>>>(N, Lo, 6, 5, 1, rows, b3, out);
    }
}

// round 9
// speedup vs baseline: 1.1412x; 1.1412x over previous
#include <cuda_runtime.h>
#include <math.h>

#define TWO_PI 6.283185307179586f
#define EPS 1e-6f
#define NEG_HALF_LOG2E (-0.7213475204444817f)

typedef unsigned long long u64;

// ---------------- device scratch ----------------
#define MAXM 120000
#define MAXS 4096
#define MAXROWS 320

__device__ float g_W[MAXM], g_PX[MAXM], g_PY[MAXM];
__device__ float g_EA[MAXM], g_EB[MAXM], g_EC[MAXM];
__device__ float g_C00[MAXM], g_C01[MAXM], g_C10[MAXM], g_C11[MAXM];
__device__ float g_W2[MAXM];

__device__ float g_SW[MAXS], g_SPX[MAXS], g_SPY[MAXS];
__device__ float g_SC00[MAXS], g_SC01[MAXS], g_SC10[MAXS], g_SC11[MAXS];

__device__ float g_TOT[MAXROWS], g_SIG[MAXROWS];
__device__ int g_tick = 0;

__device__ __forceinline__ float fast_exp2(float x) {
    float y; asm("ex2.approx.ftz.f32 %0, %1;" : "=f"(y) : "f"(x)); return y;
}
__device__ __forceinline__ float fast_sqrt(float x) {
    float y; asm("sqrt.approx.ftz.f32 %0, %1;" : "=f"(y) : "f"(x)); return y;
}
__device__ __forceinline__ float fast_rcp(float x) {
    float y; asm("rcp.approx.ftz.f32 %0, %1;" : "=f"(y) : "f"(x)); return y;
}

// ---- packed f32x2 helpers ----
__device__ __forceinline__ u64 pk2(float lo, float hi) {
    u64 r; asm("mov.b64 %0, {%1, %2};" : "=l"(r) : "f"(lo), "f"(hi)); return r;
}
__device__ __forceinline__ void upk2(u64 v, float& lo, float& hi) {
    asm("mov.b64 {%0, %1}, %2;" : "=f"(lo), "=f"(hi) : "l"(v));
}
__device__ __forceinline__ u64 add2(u64 a, u64 b) {
    u64 r; asm("add.rn.f32x2 %0, %1, %2;" : "=l"(r) : "l"(a), "l"(b)); return r;
}
__device__ __forceinline__ u64 mul2(u64 a, u64 b) {
    u64 r; asm("mul.rn.f32x2 %0, %1, %2;" : "=l"(r) : "l"(a), "l"(b)); return r;
}
__device__ __forceinline__ u64 fma2(u64 a, u64 b, u64 c) {
    u64 r; asm("fma.rn.f32x2 %0, %1, %2, %3;" : "=l"(r) : "l"(a), "l"(b), "l"(c)); return r;
}

// ---------------- conv with fused batchnorm prologue (R6 verbatim) ----------------
__global__ void k_conv(const float* __restrict__ in_x, const float* __restrict__ kern,
                       int Li, int Nd, int Lo, int Nk, int first) {
    __shared__ float s_scl[8];
    __shared__ float s_red[64];
    const int tid = threadIdx.x;
    const int b = blockIdx.y;

    if (first) {
        if (tid < 64) {
            const float* m = in_x + (b * 64 + tid) * 7;
            float det = m[3] * m[6] - m[4] * m[5];
            s_red[tid] = fabsf(m[0] * TWO_PI * fast_sqrt(fmaxf(det, EPS)));
        }
        __syncthreads();
        if (tid < 32) {
            float v = s_red[tid] + s_red[tid + 32];
            for (int o = 16; o > 0; o >>= 1) v += __shfl_xor_sync(0xffffffffu, v, o);
            if (tid == 0) s_scl[0] = 1.0f / (v + EPS);
        }
        __syncthreads();
    } else {
        if (tid < Li * 32) {
            int li = tid >> 5, bb = tid & 31;
            float v = g_TOT[bb * Li + li];
            for (int o = 16; o > 0; o >>= 1) v += __shfl_xor_sync(0xffffffffu, v, o);
            if ((tid & 31) == 0) s_scl[li] = 1.0f / (v * (1.0f / 32.0f) + EPS);
        }
        __syncthreads();
    }

    int perB = Lo * Li * Nd * Nk;
    int i = blockIdx.x * 256 + tid;
    if (i >= perB) return;
    int nk = i % Nk; int t = i / Nk;
    int nd = t % Nd; t /= Nd;
    int li = t % Li; int lo = t / Li;

    int di = (b * Li + li) * Nd + nd;
    float wd, pdx, pdy, d00, d01, d10, d11;
    if (first) {
        const float* m = in_x + di * 7;
        wd = m[0] * s_scl[0]; pdx = m[1]; pdy = m[2];
        d00 = m[3]; d01 = m[4]; d10 = m[5]; d11 = m[6];
    } else {
        wd = g_SW[di] * s_scl[li];
        pdx = g_SPX[di]; pdy = g_SPY[di];
        d00 = g_SC00[di]; d01 = g_SC01[di]; d10 = g_SC10[di]; d11 = g_SC11[di];
    }

    const float* kp = kern + (((lo * Li + li) * Nk) + nk) * 7;
    float wk = kp[0], pkx = kp[1], pky = kp[2];
    float k00 = kp[3], k01 = kp[4], k10 = kp[5], k11 = kp[6];

    float s00 = d00 + k00, s01 = d01 + k01, s10 = d10 + k10, s11 = d11 + k11;
    float dd = d00 * d11 - d01 * d10;
    float dk = k00 * k11 - k01 * k10;
    float ds = s00 * s11 - s01 * s10;
    float inv = fast_rcp(fmaxf(ds, EPS));
    float ws = wd * wk * TWO_PI * fast_sqrt(dd * dk * inv);

    int o = (b * Lo + lo) * (Li * Nd * Nk) + (li * Nd + nd) * Nk + nk;
    g_W[o] = ws;
    g_PX[o] = pdx + pkx; g_PY[o] = pdy + pky;
    g_C00[o] = s00; g_C01[o] = s01; g_C10[o] = s10; g_C11[o] = s11;
    g_EA[o] = NEG_HALF_LOG2E * s11 * inv;
    g_EB[o] = -NEG_HALF_LOG2E * (s01 + s10) * inv;
    g_EC[o] = NEG_HALF_LOG2E * s00 * inv;
}

// ---------------- eval: 2 k's per thread, waste-free chunking ----------------
// grid (nch, rows), block T. Chunk covers k in [chunk*2T, chunk*2T + 2T):
// k0 = chunk*2T + tid, k1 = k0 + T. Tile LDS.128s feed both accumulator chains.
__global__ void k_eval(int N, int Lo, const float* __restrict__ bias) {
    extern __shared__ __align__(16) float sh[];
    int Np = (N + 1) & ~1;
    int half = Np >> 1;
    float* sAf = sh;
    float* sBf = sh + 2 * Np;
    float* sCf = sh + 4 * Np;

    const int tid = threadIdx.x;
    const int T = blockDim.x;
    const int row = blockIdx.y;
    const int base = row * N;

    for (int n = tid; n < Np; n += T) {
        int j4 = (n >> 1) * 4 + (n & 1);
        if (n < N) {
            int g = base + n;
            sAf[j4] = g_PX[g]; sAf[j4 + 2] = g_PY[g];
            sBf[j4] = g_EA[g]; sBf[j4 + 2] = g_EB[g];
            sCf[j4] = g_EC[g]; sCf[j4 + 2] = g_W[g];
        } else {
            sAf[j4] = 0.0f; sAf[j4 + 2] = 0.0f;
            sBf[j4] = 0.0f; sBf[j4 + 2] = 0.0f;
            sCf[j4] = 0.0f; sCf[j4 + 2] = 0.0f;
        }
    }
    __syncthreads();

    const int k0 = blockIdx.x * (2 * T) + tid;
    const int k1 = k0 + T;
    if (k0 >= N) return;
    const int k1c = (k1 < N) ? k1 : k0;

    int k04 = (k0 >> 1) * 4 + (k0 & 1);
    int k14 = (k1c >> 1) * 4 + (k1c & 1);
    float kx0 = sAf[k04], ky0 = sAf[k04 + 2], w0 = sCf[k04 + 2];
    float kx1 = sAf[k14], ky1 = sAf[k14 + 2], w1 = sCf[k14 + 2];
    u64 nkx0 = pk2(-kx0, -kx0), nky0 = pk2(-ky0, -ky0);
    u64 nkx1 = pk2(-kx1, -kx1), nky1 = pk2(-ky1, -ky1);
    u64 acc0 = 0ull, acc1 = 0ull;

    const float4* sA = (const float4*)sAf;
    const float4* sB = (const float4*)sBf;
    const float4* sC = (const float4*)sCf;

    #pragma unroll 4
    for (int j = 0; j < half; j++) {
        float4 a = sA[j];
        float4 bq = sB[j];
        float4 c = sC[j];
        u64 px2 = *(const u64*)&a.x;  u64 py2 = *(const u64*)&a.z;
        u64 ea2 = *(const u64*)&bq.x; u64 eb2 = *(const u64*)&bq.z;
        u64 ec2 = *(const u64*)&c.x;  u64 w2p = *(const u64*)&c.z;

        u64 dx0 = add2(px2, nkx0);
        u64 dy0 = add2(py2, nky0);
        u64 u0  = fma2(ea2, dx0, mul2(eb2, dy0));
        u64 md0 = fma2(dx0, u0, mul2(mul2(ec2, dy0), dy0));
        u64 dx1 = add2(px2, nkx1);
        u64 dy1 = add2(py2, nky1);
        u64 u1  = fma2(ea2, dx1, mul2(eb2, dy1));
        u64 md1 = fma2(dx1, u1, mul2(mul2(ec2, dy1), dy1));
        float m0, m1, m2, m3;
        upk2(md0, m0, m1); upk2(md1, m2, m3);
        u64 e0 = pk2(fast_exp2(m0), fast_exp2(m1));
        u64 e1 = pk2(fast_exp2(m2), fast_exp2(m3));
        acc0 = fma2(w2p, e0, acc0);
        acc1 = fma2(w2p, e1, acc1);
    }

    float bs = bias[row % Lo];
    float a0, a1; upk2(acc0, a0, a1);
    float v0 = a0 + a1 + bs;
    g_W2[base + k0] = w0 * (fmaxf(v0, 0.0f) * fast_rcp(fabsf(v0) + EPS));
    if (k1 < N) {
        float b0, b1v; upk2(acc1, b0, b1v);
        float v1 = b0 + b1v + bs;
        g_W2[base + k1] = w1 * (fmaxf(v1, 0.0f) * fast_rcp(fabsf(v1) + EPS));
    }
}

// ---------------- two-level rank top-k (R6 verbatim) ----------------
__global__ void k_topk(int N, int nchunks, int nsel, int do_final, int rows,
                       float* __restrict__ out) {
    const int tid = threadIdx.x;
    const int row = blockIdx.x;
    const int base = row * N;
    const int NC = nchunks * 64;

    __shared__ __align__(16) u64 keys[640];
    __shared__ __align__(16) u64 sCand[136];
    __shared__ int s_cnt;
    __shared__ float s_out[64];
    __shared__ int s_last;
    __shared__ float scl[10];
    __shared__ float logit[320];

    if (tid == 0) s_cnt = 0;
    for (int n = tid; n < NC; n += blockDim.x) {
        keys[n] = (n < N)
            ? (((u64)__float_as_uint(fabsf(g_W2[base + n])) << 32) | (u64)(unsigned)(~(unsigned)n))
            : 0ull;
    }
    __syncthreads();

    // level 1: per-warp chunk rank
    {
        int w = tid >> 5, lane = tid & 31;
        int kb = w << 6;
        u64 k0 = keys[kb + lane];
        u64 k1 = keys[kb + lane + 32];
        int r0 = 0, r1 = 0;
        const ulonglong2* Q = (const ulonglong2*)(keys + kb);
        #pragma unroll 8
        for (int j = 0; j < 32; j++) {
            ulonglong2 q = Q[j];
            r0 += (int)(q.x > k0) + (int)(q.y > k0);
            r1 += (int)(q.x > k1) + (int)(q.y > k1);
        }
        if (kb + lane < N && r0 < nsel)      { int s = atomicAdd(&s_cnt, 1); sCand[s] = k0; }
        if (kb + lane + 32 < N && r1 < nsel) { int s = atomicAdd(&s_cnt, 1); sCand[s] = k1; }
    }
    __syncthreads();
    int m = s_cnt;
    if (tid == 0 && (m & 1)) sCand[m] = 0ull;
    __syncthreads();

    // level 2: exact rank among candidates
    {
        int mq = (m + 1) >> 1;
        const ulonglong2* Q = (const ulonglong2*)sCand;
        for (int i = tid; i < m; i += blockDim.x) {
            u64 mykey = sCand[i];
            int rank = 0;
            #pragma unroll 4
            for (int j = 0; j < mq; j++) {
                ulonglong2 q = Q[j];
                rank += (int)(q.x > mykey) + (int)(q.y > mykey);
            }
            if (rank < nsel) {
                int n = (int)(~(unsigned)mykey);
                int src = base + n;
                int dst = row * nsel + rank;
                float wv = g_W2[src];
                float c00 = g_C00[src], c01 = g_C01[src], c10 = g_C10[src], c11 = g_C11[src];
                g_SW[dst] = wv;
                g_SPX[dst] = g_PX[src]; g_SPY[dst] = g_PY[src];
                g_SC00[dst] = c00; g_SC01[dst] = c01;
                g_SC10[dst] = c10; g_SC11[dst] = c11;
                float I = wv * TWO_PI * fast_sqrt(fmaxf(c00 * c11 - c01 * c10, EPS));
                s_out[rank] = fabsf(I);
                s_out[32 + rank] = I;
            }
        }
    }
    __syncthreads();
    if (tid == 0) {
        float tot = 0.0f, sg = 0.0f;
        for (int t = 0; t < nsel; t++) { tot += s_out[t]; sg += s_out[32 + t]; }
        g_TOT[row] = tot;
        if (do_final) g_SIG[row] = sg;
    }

    if (!do_final) return;

    // fused finale
    if (tid == 0) {
        __threadfence();
        int t = atomicAdd(&g_tick, 1);
        s_last = (t == rows - 1) ? 1 : 0;
        if (s_last) g_tick = 0;
    }
    __syncthreads();
    if (!s_last) return;
    __threadfence();

    if (tid < 10) {
        float t = 0.0f;
        for (int b = 0; b < 32; b++) t += g_TOT[b * 10 + tid];
        scl[tid] = 1.0f / (t / 32.0f + EPS);
    }
    __syncthreads();
    for (int i = tid; i < 320; i += blockDim.x) logit[i] = g_SIG[i] * scl[i % 10];
    __syncthreads();
    if (tid < 32) {
        int b = tid;
        float mx = -INFINITY;
        for (int l = 0; l < 10; l++) mx = fmaxf(mx, logit[b * 10 + l]);
        float se = 0.0f;
        for (int l = 0; l < 10; l++) se += expf(logit[b * 10 + l] - mx);
        float lse = mx + logf(se);
        for (int l = 0; l < 10; l++) out[b * 10 + l] = logit[b * 10 + l] - lse;
    }
}

extern "C" void kernel_launch(void* const* d_in, const int* in_sizes, int n_in,
                              void* d_out, int out_size) {
    const float* in_x = (const float*)d_in[0];
    const float* k1 = (const float*)d_in[1];
    const float* k2 = (const float*)d_in[2];
    const float* k3 = (const float*)d_in[3];
    const float* b1 = (const float*)d_in[4];
    const float* b2 = (const float*)d_in[5];
    const float* b3 = (const float*)d_in[6];
    float* out = (float*)d_out;
    const int B = 32;

    // ===== layer 1: Li=1, Nd=64, Lo=5, Nk=5 -> N=320, rows=160, nsel=25 =====
    {
        int Li = 1, Nd = 64, Lo = 5, Nk = 5;
        int N = 320, rows = 160, perB = Lo * N;
        int Np = (N + 1) & ~1, nch = (N + 63) / 64;
        k_conv<<<dim3((perB + 255) / 256, B), 256>>>(in_x, k1, Li, Nd, Lo, Nk, 1);
        // T=160, 2T=320 = N exactly -> 1 eval chunk per row
        k_eval<<<dim3(1, rows), 160, Np * 24>>>(N, Lo, b1);
        k_topk<<<rows, 32 * nch>>>(N, nch, 25, 0, rows, out);
    }

    // ===== layer 2: Li=5, Nd=25, Lo=6, Nk=5 -> N=625, rows=192, nsel=12 =====
    {
        int Li = 5, Nd = 25, Lo = 6, Nk = 5;
        int N = 625, rows = 192, perB = Lo * Li * Nd * Nk;
        int Np = (N + 1) & ~1, nch = (N + 63) / 64;
        k_conv<<<dim3((perB + 255) / 256, B), 256>>>(in_x, k2, Li, Nd, Lo, Nk, 0);
        // T=160, 2T=320 -> 2 eval chunks cover 640 >= 625 (2% waste), 384 blocks
        k_eval<<<dim3(2, rows), 160, Np * 24>>>(N, Lo, b2);
        k_topk<<<rows, 32 * nch>>>(N, nch, 12, 0, rows, out);
    }

    // ===== layer 3: Li=6, Nd=12, Lo=10, Nk=5 -> N=360, rows=320, nsel=5 =====
    {
        int Li = 6, Nd = 12, Lo = 10, Nk = 5;
        int N = 360, rows = 320, perB = Lo * Li * Nd * Nk;
        int Np = (N + 1) & ~1, nch = (N + 63) / 64;
        k_conv<<<dim3((perB + 255) / 256, B), 256>>>(in_x, k3, Li, Nd, Lo, Nk, 0);
        // T=192, 2T=384 >= 360 (7% waste) -> 1 eval chunk per row, 320 blocks
        k_eval<<<dim3(1, rows), 192, Np * 24>>>(N, Lo, b3);
        k_topk<<<rows, 32 * nch>>>(N, nch, 5, 1, rows, out);
    }
}

// round 10
// speedup vs baseline: 1.1415x; 1.0003x over previous
#include <cuda_runtime.h>
#include <math.h>

#define TWO_PI 6.283185307179586f
#define EPS 1e-6f
#define NEG_HALF_LOG2E (-0.7213475204444817f)

typedef unsigned long long u64;

// ---------------- device scratch ----------------
#define MAXM 120000
#define MAXS 4096
#define MAXROWS 320

__device__ float g_W[MAXM], g_PX[MAXM], g_PY[MAXM];
__device__ float g_EA[MAXM], g_EB[MAXM], g_EC[MAXM];
__device__ float g_C00[MAXM], g_C01[MAXM], g_C10[MAXM], g_C11[MAXM];
__device__ float g_W2[MAXM];

__device__ float g_SW[MAXS], g_SPX[MAXS], g_SPY[MAXS];
__device__ float g_SC00[MAXS], g_SC01[MAXS], g_SC10[MAXS], g_SC11[MAXS];

__device__ float g_TOT[MAXROWS], g_SIG[MAXROWS];
__device__ int g_rowtick[MAXROWS];  // zero-init; self-resetting
__device__ int g_tick = 0;          // finale ticket; self-resetting

__device__ __forceinline__ float fast_exp2(float x) {
    float y; asm("ex2.approx.ftz.f32 %0, %1;" : "=f"(y) : "f"(x)); return y;
}
__device__ __forceinline__ float fast_sqrt(float x) {
    float y; asm("sqrt.approx.ftz.f32 %0, %1;" : "=f"(y) : "f"(x)); return y;
}
__device__ __forceinline__ float fast_rcp(float x) {
    float y; asm("rcp.approx.ftz.f32 %0, %1;" : "=f"(y) : "f"(x)); return y;
}

// ---- packed f32x2 helpers ----
__device__ __forceinline__ u64 pk2(float lo, float hi) {
    u64 r; asm("mov.b64 %0, {%1, %2};" : "=l"(r) : "f"(lo), "f"(hi)); return r;
}
__device__ __forceinline__ void upk2(u64 v, float& lo, float& hi) {
    asm("mov.b64 {%0, %1}, %2;" : "=f"(lo), "=f"(hi) : "l"(v));
}
__device__ __forceinline__ u64 add2(u64 a, u64 b) {
    u64 r; asm("add.rn.f32x2 %0, %1, %2;" : "=l"(r) : "l"(a), "l"(b)); return r;
}
__device__ __forceinline__ u64 mul2(u64 a, u64 b) {
    u64 r; asm("mul.rn.f32x2 %0, %1, %2;" : "=l"(r) : "l"(a), "l"(b)); return r;
}
__device__ __forceinline__ u64 fma2(u64 a, u64 b, u64 c) {
    u64 r; asm("fma.rn.f32x2 %0, %1, %2, %3;" : "=l"(r) : "l"(a), "l"(b), "l"(c)); return r;
}

// ---------------- conv with fused batchnorm prologue (R6 verbatim) ----------------
__global__ void k_conv(const float* __restrict__ in_x, const float* __restrict__ kern,
                       int Li, int Nd, int Lo, int Nk, int first) {
    __shared__ float s_scl[8];
    __shared__ float s_red[64];
    const int tid = threadIdx.x;
    const int b = blockIdx.y;

    if (first) {
        if (tid < 64) {
            const float* m = in_x + (b * 64 + tid) * 7;
            float det = m[3] * m[6] - m[4] * m[5];
            s_red[tid] = fabsf(m[0] * TWO_PI * fast_sqrt(fmaxf(det, EPS)));
        }
        __syncthreads();
        if (tid < 32) {
            float v = s_red[tid] + s_red[tid + 32];
            for (int o = 16; o > 0; o >>= 1) v += __shfl_xor_sync(0xffffffffu, v, o);
            if (tid == 0) s_scl[0] = 1.0f / (v + EPS);
        }
        __syncthreads();
    } else {
        if (tid < Li * 32) {
            int li = tid >> 5, bb = tid & 31;
            float v = g_TOT[bb * Li + li];
            for (int o = 16; o > 0; o >>= 1) v += __shfl_xor_sync(0xffffffffu, v, o);
            if ((tid & 31) == 0) s_scl[li] = 1.0f / (v * (1.0f / 32.0f) + EPS);
        }
        __syncthreads();
    }

    int perB = Lo * Li * Nd * Nk;
    int i = blockIdx.x * 256 + tid;
    if (i >= perB) return;
    int nk = i % Nk; int t = i / Nk;
    int nd = t % Nd; t /= Nd;
    int li = t % Li; int lo = t / Li;

    int di = (b * Li + li) * Nd + nd;
    float wd, pdx, pdy, d00, d01, d10, d11;
    if (first) {
        const float* m = in_x + di * 7;
        wd = m[0] * s_scl[0]; pdx = m[1]; pdy = m[2];
        d00 = m[3]; d01 = m[4]; d10 = m[5]; d11 = m[6];
    } else {
        wd = g_SW[di] * s_scl[li];
        pdx = g_SPX[di]; pdy = g_SPY[di];
        d00 = g_SC00[di]; d01 = g_SC01[di]; d10 = g_SC10[di]; d11 = g_SC11[di];
    }

    const float* kp = kern + (((lo * Li + li) * Nk) + nk) * 7;
    float wk = kp[0], pkx = kp[1], pky = kp[2];
    float k00 = kp[3], k01 = kp[4], k10 = kp[5], k11 = kp[6];

    float s00 = d00 + k00, s01 = d01 + k01, s10 = d10 + k10, s11 = d11 + k11;
    float dd = d00 * d11 - d01 * d10;
    float dk = k00 * k11 - k01 * k10;
    float ds = s00 * s11 - s01 * s10;
    float inv = fast_rcp(fmaxf(ds, EPS));
    float ws = wd * wk * TWO_PI * fast_sqrt(dd * dk * inv);

    int o = (b * Lo + lo) * (Li * Nd * Nk) + (li * Nd + nd) * Nk + nk;
    g_W[o] = ws;
    g_PX[o] = pdx + pkx; g_PY[o] = pdy + pky;
    g_C00[o] = s00; g_C01[o] = s01; g_C10[o] = s10; g_C11[o] = s11;
    g_EA[o] = NEG_HALF_LOG2E * s11 * inv;
    g_EB[o] = -NEG_HALF_LOG2E * (s01 + s10) * inv;
    g_EC[o] = NEG_HALF_LOG2E * s00 * inv;
}

// ================= eval (R6 geometry) + ticket topk epilogue =================
// grid (evchunks=ceil(N/128), rows), block 128. Eval identical to R6's k_eval.
// After eval, last block of each row (atomic ticket) runs two-level rank topk
// for the row, overlapped with other rows' eval. Layer 3 last-of-all-rows
// block additionally runs the finale.
__global__ __launch_bounds__(128) void k_evaltopk(
    int N, int Lo, int nch, int nsel, int do_final, int rows,
    const float* __restrict__ bias, float* __restrict__ out)
{
    extern __shared__ __align__(16) float sh[];
    const int Np = (N + 1) & ~1;
    const int half = Np >> 1;
    float* sAf = sh;
    float* sBf = sh + 2 * Np;
    float* sCf = sh + 4 * Np;

    __shared__ __align__(16) u64 sCand[136];
    __shared__ int s_cnt, s_go, s_last;
    __shared__ float s_out[64];
    __shared__ float scl[10];
    __shared__ float logit[320];

    const int tid = threadIdx.x;
    const int row = blockIdx.y;
    const int base = row * N;

    // ---- tile load (pair-interleaved) ----
    for (int n = tid; n < Np; n += 128) {
        int j4 = (n >> 1) * 4 + (n & 1);
        if (n < N) {
            int g = base + n;
            sAf[j4] = g_PX[g]; sAf[j4 + 2] = g_PY[g];
            sBf[j4] = g_EA[g]; sBf[j4 + 2] = g_EB[g];
            sCf[j4] = g_EC[g]; sCf[j4 + 2] = g_W[g];
        } else {
            sAf[j4] = 0.0f; sAf[j4 + 2] = 0.0f;
            sBf[j4] = 0.0f; sBf[j4 + 2] = 0.0f;
            sCf[j4] = 0.0f; sCf[j4 + 2] = 0.0f;
        }
    }
    __syncthreads();

    // ---- eval (single-k per thread, R6 inner loop) ----
    int k = blockIdx.x * 128 + tid;
    if (k < N) {
        int k4 = (k >> 1) * 4 + (k & 1);
        float kx = sAf[k4], ky = sAf[k4 + 2];
        float wk = sCf[k4 + 2];
        u64 nkx2 = pk2(-kx, -kx);
        u64 nky2 = pk2(-ky, -ky);
        u64 acc = 0ull;

        const float4* sA = (const float4*)sAf;
        const float4* sB = (const float4*)sBf;
        const float4* sC = (const float4*)sCf;

        #pragma unroll 4
        for (int j = 0; j < half; j++) {
            float4 a = sA[j];
            float4 bq = sB[j];
            float4 c = sC[j];
            u64 px2 = *(const u64*)&a.x;  u64 py2 = *(const u64*)&a.z;
            u64 ea2 = *(const u64*)&bq.x; u64 eb2 = *(const u64*)&bq.z;
            u64 ec2 = *(const u64*)&c.x;  u64 w2p = *(const u64*)&c.z;

            u64 dx = add2(px2, nkx2);
            u64 dy = add2(py2, nky2);
            u64 u  = fma2(ea2, dx, mul2(eb2, dy));
            u64 md = fma2(dx, u, mul2(mul2(ec2, dy), dy));
            float m0, m1; upk2(md, m0, m1);
            u64 e = pk2(fast_exp2(m0), fast_exp2(m1));
            acc = fma2(w2p, e, acc);
        }

        float a0, a1; upk2(acc, a0, a1);
        float v = a0 + a1 + bias[row % Lo];
        float scale = fmaxf(v, 0.0f) * fast_rcp(fabsf(v) + EPS);
        g_W2[base + k] = wk * scale;
    }

    // ---- row ticket: last eval block of this row runs the topk epilogue ----
    __threadfence();
    __syncthreads();
    if (tid == 0) {
        int t = atomicAdd(&g_rowtick[row], 1);
        s_go = (t == (int)gridDim.x - 1);
        if (s_go) g_rowtick[row] = 0;  // self-reset for graph replay
    }
    __syncthreads();
    if (!s_go) return;
    __threadfence();

    // ---- topk epilogue: keys overlay the (dead) eval tile smem ----
    u64* keys = (u64*)sh;
    const int NC = nch * 64;
    if (tid == 0) s_cnt = 0;
    for (int n = tid; n < NC; n += 128) {
        keys[n] = (n < N)
            ? (((u64)__float_as_uint(fabsf(g_W2[base + n])) << 32) | (u64)(unsigned)(~(unsigned)n))
            : 0ull;
    }
    __syncthreads();

    // level 1: warps loop over 64-wide chunks
    {
        int w = tid >> 5, lane = tid & 31;
        for (int c = w; c < nch; c += 4) {
            int kb = c << 6;
            u64 k0 = keys[kb + lane];
            u64 k1 = keys[kb + lane + 32];
            int r0 = 0, r1 = 0;
            const ulonglong2* Q = (const ulonglong2*)(keys + kb);
            #pragma unroll 8
            for (int j = 0; j < 32; j++) {
                ulonglong2 q = Q[j];
                r0 += (int)(q.x > k0) + (int)(q.y > k0);
                r1 += (int)(q.x > k1) + (int)(q.y > k1);
            }
            if (kb + lane < N && r0 < nsel)      { int s = atomicAdd(&s_cnt, 1); sCand[s] = k0; }
            if (kb + lane + 32 < N && r1 < nsel) { int s = atomicAdd(&s_cnt, 1); sCand[s] = k1; }
        }
    }
    __syncthreads();
    int m = s_cnt;
    if (tid == 0 && (m & 1)) sCand[m] = 0ull;
    __syncthreads();

    // level 2: exact rank among candidates + gather
    {
        int mq = (m + 1) >> 1;
        const ulonglong2* Q = (const ulonglong2*)sCand;
        for (int i = tid; i < m; i += 128) {
            u64 mykey = sCand[i];
            int rank = 0;
            #pragma unroll 4
            for (int j = 0; j < mq; j++) {
                ulonglong2 q = Q[j];
                rank += (int)(q.x > mykey) + (int)(q.y > mykey);
            }
            if (rank < nsel) {
                int n = (int)(~(unsigned)mykey);
                int src = base + n;
                int dst = row * nsel + rank;
                float wv = g_W2[src];
                float c00 = g_C00[src], c01 = g_C01[src], c10 = g_C10[src], c11 = g_C11[src];
                g_SW[dst] = wv;
                g_SPX[dst] = g_PX[src]; g_SPY[dst] = g_PY[src];
                g_SC00[dst] = c00; g_SC01[dst] = c01;
                g_SC10[dst] = c10; g_SC11[dst] = c11;
                float I = wv * TWO_PI * fast_sqrt(fmaxf(c00 * c11 - c01 * c10, EPS));
                s_out[rank] = fabsf(I);
                s_out[32 + rank] = I;
            }
        }
    }
    __syncthreads();
    if (tid == 0) {
        float tot = 0.0f, sg = 0.0f;
        for (int t = 0; t < nsel; t++) { tot += s_out[t]; sg += s_out[32 + t]; }
        g_TOT[row] = tot;
        if (do_final) g_SIG[row] = sg;
    }

    if (!do_final) return;

    // ---- finale ticket: last row's epilogue block runs bn + integrate + log_softmax ----
    if (tid == 0) {
        __threadfence();
        int t = atomicAdd(&g_tick, 1);
        s_last = (t == rows - 1) ? 1 : 0;
        if (s_last) g_tick = 0;
    }
    __syncthreads();
    if (!s_last) return;
    __threadfence();

    if (tid < 10) {
        float t = 0.0f;
        for (int b = 0; b < 32; b++) t += g_TOT[b * 10 + tid];
        scl[tid] = 1.0f / (t / 32.0f + EPS);
    }
    __syncthreads();
    for (int i = tid; i < 320; i += 128) logit[i] = g_SIG[i] * scl[i % 10];
    __syncthreads();
    if (tid < 32) {
        int b = tid;
        float mx = -INFINITY;
        for (int l = 0; l < 10; l++) mx = fmaxf(mx, logit[b * 10 + l]);
        float se = 0.0f;
        for (int l = 0; l < 10; l++) se += expf(logit[b * 10 + l] - mx);
        float lse = mx + logf(se);
        for (int l = 0; l < 10; l++) out[b * 10 + l] = logit[b * 10 + l] - lse;
    }
}

extern "C" void kernel_launch(void* const* d_in, const int* in_sizes, int n_in,
                              void* d_out, int out_size) {
    const float* in_x = (const float*)d_in[0];
    const float* k1 = (const float*)d_in[1];
    const float* k2 = (const float*)d_in[2];
    const float* k3 = (const float*)d_in[3];
    const float* b1 = (const float*)d_in[4];
    const float* b2 = (const float*)d_in[5];
    const float* b3 = (const float*)d_in[6];
    float* out = (float*)d_out;
    const int B = 32;

    // ===== layer 1: Li=1, Nd=64, Lo=5, Nk=5 -> N=320, rows=160, nsel=25 =====
    {
        int Li = 1, Nd = 64, Lo = 5, Nk = 5;
        int N = 320, rows = 160, perB = Lo * N;
        int Np = (N + 1) & ~1, nch = (N + 63) / 64;
        k_conv<<<dim3((perB + 255) / 256, B), 256>>>(in_x, k1, Li, Nd, Lo, Nk, 1);
        k_evaltopk<<<dim3((N + 127) / 128, rows), 128, Np * 24>>>(
            N, Lo, nch, 25, 0, rows, b1, out);
    }

    // ===== layer 2: Li=5, Nd=25, Lo=6, Nk=5 -> N=625, rows=192, nsel=12 =====
    {
        int Li = 5, Nd = 25, Lo = 6, Nk = 5;
        int N = 625, rows = 192, perB = Lo * Li * Nd * Nk;
        int Np = (N + 1) & ~1, nch = (N + 63) / 64;
        k_conv<<<dim3((perB + 255) / 256, B), 256>>>(in_x, k2, Li, Nd, Lo, Nk, 0);
        k_evaltopk<<<dim3((N + 127) / 128, rows), 128, Np * 24>>>(
            N, Lo, nch, 12, 0, rows, b2, out);
    }

    // ===== layer 3: Li=6, Nd=12, Lo=10, Nk=5 -> N=360, rows=320, nsel=5 =====
    {
        int Li = 6, Nd = 12, Lo = 10, Nk = 5;
        int N = 360, rows = 320, perB = Lo * Li * Nd * Nk;
        int Np = (N + 1) & ~1, nch = (N + 63) / 64;
        k_conv<<<dim3((perB + 255) / 256, B), 256>>>(in_x, k3, Li, Nd, Lo, Nk, 0);
        k_evaltopk<<<dim3((N + 127) / 128, rows), 128, Np * 24>>>(
            N, Lo, nch, 5, 1, rows, b3, out);
    }
}